// round 14
// baseline (speedup 1.0000x reference)
#include <cuda_runtime.h>
#include <math.h>
#include <stdint.h>

// Problem constants
#define BB 2
#define SS 2048
#define CC 1024
#define HH 16
#define DD 64
#define GG 4
#define ICG 256
#define OCG 256

__device__ float g_q[BB * SS * CC];
__device__ float g_k[BB * SS * CC];
__device__ float g_v[BB * SS * CC];

// ---------------------------------------------------------------------------
// helpers
// ---------------------------------------------------------------------------
__device__ __forceinline__ uint32_t f2tf32(float x) {
    uint32_t u;
    asm("cvt.rna.tf32.f32 %0, %1;" : "=r"(u) : "f"(x));
    return u;
}
__device__ __forceinline__ float f2tf32f(float x) {
    return __uint_as_float(f2tf32(x));
}
__device__ __forceinline__ uint32_t smem_u32(const void* p) {
    uint32_t a;
    asm("{ .reg .u64 t; cvta.to.shared.u64 t, %1; cvt.u32.u64 %0, t; }"
        : "=r"(a) : "l"(p));
    return a;
}
#define CP_ASYNC16(dst_u32, src_ptr) \
    asm volatile("cp.async.ca.shared.global [%0], [%1], 16;" \
                 :: "r"(dst_u32), "l"(src_ptr))
#define CP_COMMIT() asm volatile("cp.async.commit_group;")
#define CP_WAIT0()  asm volatile("cp.async.wait_group 0;")

__device__ __forceinline__ void mma_tf32(float d[4], uint32_t a0, uint32_t a1,
                                         uint32_t a2, uint32_t a3,
                                         uint32_t b0, uint32_t b1) {
    asm volatile(
        "mma.sync.aligned.m16n8k8.row.col.f32.tf32.tf32.f32 "
        "{%0,%1,%2,%3}, {%4,%5,%6,%7}, {%8,%9}, {%0,%1,%2,%3};"
        : "+f"(d[0]), "+f"(d[1]), "+f"(d[2]), "+f"(d[3])
        : "r"(a0), "r"(a1), "r"(a2), "r"(a3), "r"(b0), "r"(b1));
}

// ---------------------------------------------------------------------------
// Grouped linear projection on tensor cores (tf32 warp-mma) — unchanged R10-13.
// ---------------------------------------------------------------------------
#define PSTRA 36
#define PSTRB 136

__global__ __launch_bounds__(256) void proj_kernel(
    const float* __restrict__ qin, const float* __restrict__ kin,
    const float* __restrict__ vin,
    const float* __restrict__ wq, const float* __restrict__ wk,
    const float* __restrict__ wv,
    const float* __restrict__ bq, const float* __restrict__ bk,
    const float* __restrict__ bv)
{
    const float* src; const float* w; const float* bias; float* out;
    if (blockIdx.z == 0)      { src = qin; w = wq; bias = bq; out = g_q; }
    else if (blockIdx.z == 1) { src = kin; w = wk; bias = bk; out = g_k; }
    else                      { src = vin; w = wv; bias = bv; out = g_v; }

    const int row0 = blockIdx.x * 128;
    const int col0 = blockIdx.y * 128;
    const int g    = col0 / OCG;
    const int nb   = col0 % OCG;

    __shared__ float As[128 * PSTRA];
    __shared__ float Bs[32 * PSTRB];

    const int tid  = threadIdx.x;
    const int lane = tid & 31;
    const int warp = tid >> 5;
    const int gid  = lane >> 2;
    const int qid  = lane & 3;
    const int wm   = (warp >> 1) * 32;
    const int wn   = (warp & 1) * 64;

    float acc[2][8][4];
#pragma unroll
    for (int f = 0; f < 2; f++)
#pragma unroll
        for (int nt = 0; nt < 8; nt++)
#pragma unroll
            for (int j = 0; j < 4; j++) acc[f][nt][j] = 0.0f;

    const float* srcb = src + (size_t)row0 * CC + g * ICG;
    const float* wb   = w + (size_t)g * ICG * OCG + nb;

    for (int k0 = 0; k0 < ICG; k0 += 32) {
        for (int e = tid; e < 128 * 32; e += 256) {
            int r = e >> 5, kk = e & 31;
            As[r * PSTRA + kk] = f2tf32f(srcb[(size_t)r * CC + k0 + kk]);
        }
        for (int e = tid; e < 32 * 128; e += 256) {
            int kk = e >> 7, n = e & 127;
            Bs[kk * PSTRB + n] = f2tf32f(wb[(size_t)(k0 + kk) * OCG + n]);
        }
        __syncthreads();

#pragma unroll
        for (int kt = 0; kt < 4; kt++) {
            uint32_t a[2][4];
#pragma unroll
            for (int f = 0; f < 2; f++) {
                int rb = wm + f * 16;
                a[f][0] = __float_as_uint(As[(rb + gid)     * PSTRA + kt * 8 + qid]);
                a[f][1] = __float_as_uint(As[(rb + gid + 8) * PSTRA + kt * 8 + qid]);
                a[f][2] = __float_as_uint(As[(rb + gid)     * PSTRA + kt * 8 + qid + 4]);
                a[f][3] = __float_as_uint(As[(rb + gid + 8) * PSTRA + kt * 8 + qid + 4]);
            }
#pragma unroll
            for (int nt = 0; nt < 8; nt++) {
                uint32_t b0 = __float_as_uint(Bs[(kt * 8 + qid)     * PSTRB + wn + nt * 8 + gid]);
                uint32_t b1 = __float_as_uint(Bs[(kt * 8 + qid + 4) * PSTRB + wn + nt * 8 + gid]);
                mma_tf32(acc[0][nt], a[0][0], a[0][1], a[0][2], a[0][3], b0, b1);
                mma_tf32(acc[1][nt], a[1][0], a[1][1], a[1][2], a[1][3], b0, b1);
            }
        }
        __syncthreads();
    }

#pragma unroll
    for (int f = 0; f < 2; f++) {
        int rb = row0 + wm + f * 16;
#pragma unroll
        for (int nt = 0; nt < 8; nt++) {
            int c = col0 + wn + nt * 8 + 2 * qid;
            float b0v = bias[c], b1v = bias[c + 1];
            *(float2*)&out[(size_t)(rb + gid) * CC + c] =
                make_float2(acc[f][nt][0] + b0v, acc[f][nt][1] + b1v);
            *(float2*)&out[(size_t)(rb + gid + 8) * CC + c] =
                make_float2(acc[f][nt][2] + b0v, acc[f][nt][3] + b1v);
        }
    }
}

// ---------------------------------------------------------------------------
// Flash attention v4: M=16/warp, 256 threads (16 warps/SM at 2 CTAs/SM),
// Q in registers, no-max restricted softmax (out = exp(s)/(sum exp(s)+1);
// max subtraction cancels algebraically, |s| <~ 3 so no overflow),
// streaming S->P, double-buffered cp.async K/V fills.
// CTA: 256 threads (8 warps), Q-tile 128 rows (16/warp), K/V tile 64.
// Smem: 2 x (K 64x68 + V 64x72) + Ps 128x68 = 106,496 B -> 2 CTAs/SM.
// Grid: (16, 16, 2).
// ---------------------------------------------------------------------------
#define KTILE 64
#define SK 68
#define SV 72
#define FK0 0
#define FV0 (KTILE * SK)                 // 4352
#define FK1 (FV0 + KTILE * SV)           // 8960
#define FV1 (FK1 + KTILE * SK)           // 13312
#define FPS (FV1 + KTILE * SV)           // 17920
#define ATTN_SMEM ((FPS + 128 * SK) * 4) // 106,496 B
#define NTILE (SS / KTILE)

__global__ __launch_bounds__(256, 2) void attn_kernel(float* __restrict__ out)
{
    extern __shared__ float sm[];
    const uint32_t sb = smem_u32(sm);

    const int qt = blockIdx.x;
    const int h  = blockIdx.y;
    const int b  = blockIdx.z;

    const int tid  = threadIdx.x;
    const int lane = tid & 31;
    const int warp = tid >> 5;
    const int gid  = lane >> 2;
    const int qid  = lane & 3;
    const int w16  = warp * 16;

    const float scale = 0.125f;   // 1/sqrt(64)

    const float* qb  = g_q + ((size_t)b * SS + qt * 128) * CC + h * DD;
    const float* kbb = g_k + (size_t)b * SS * CC + h * DD;
    const float* vbb = g_v + (size_t)b * SS * CC + h * DD;

    // Prologue: stage Q into buf1 region (8704 <= 8960 floats), K/V t=0 -> buf0.
#pragma unroll
    for (int e = tid; e < 128 * 16; e += 256) {
        int r = e >> 4, c4 = (e & 15) * 4;
        CP_ASYNC16(sb + (FK1 + r * SK + c4) * 4, qb + (size_t)r * CC + c4);
    }
    CP_COMMIT();
#pragma unroll
    for (int e = tid; e < KTILE * 16; e += 256) {
        int r = e >> 4, c4 = (e & 15) * 4;
        CP_ASYNC16(sb + (FK0 + r * SK + c4) * 4, kbb + (size_t)r * CC + c4);
        CP_ASYNC16(sb + (FV0 + r * SV + c4) * 4, vbb + (size_t)r * CC + c4);
    }
    CP_COMMIT();
    CP_WAIT0();
    __syncthreads();

    // Q fragments -> registers (held for all 32 tiles). 32 regs.
    uint32_t qa[8][4];
#pragma unroll
    for (int kt = 0; kt < 8; kt++) {
        qa[kt][0] = __float_as_uint(sm[FK1 + (w16 + gid)     * SK + kt * 8 + qid]);
        qa[kt][1] = __float_as_uint(sm[FK1 + (w16 + gid + 8) * SK + kt * 8 + qid]);
        qa[kt][2] = __float_as_uint(sm[FK1 + (w16 + gid)     * SK + kt * 8 + qid + 4]);
        qa[kt][3] = __float_as_uint(sm[FK1 + (w16 + gid + 8) * SK + kt * 8 + qid + 4]);
    }
    __syncthreads();   // buf1 free for t=1 prefetch

    float o[8][4];
    float lA = 0.0f, lB = 0.0f;
#pragma unroll
    for (int nt = 0; nt < 8; nt++)
#pragma unroll
        for (int j = 0; j < 4; j++) o[nt][j] = 0.0f;

    for (int t = 0; t < NTILE; t++) {
        const int cur = t & 1;
        const int fk  = cur ? FK1 : FK0;
        const int fv  = cur ? FV1 : FV0;

        // Prefetch tile t+1 into the other buffer (hidden behind compute).
        if (t + 1 < NTILE) {
            const int nfk = cur ? FK0 : FK1;
            const int nfv = cur ? FV0 : FV1;
            const float* kn = kbb + (size_t)(t + 1) * KTILE * CC;
            const float* vn = vbb + (size_t)(t + 1) * KTILE * CC;
#pragma unroll
            for (int e = tid; e < KTILE * 16; e += 256) {
                int r = e >> 4, c4 = (e & 15) * 4;
                CP_ASYNC16(sb + (nfk + r * SK + c4) * 4, kn + (size_t)r * CC + c4);
                CP_ASYNC16(sb + (nfv + r * SV + c4) * 4, vn + (size_t)r * CC + c4);
            }
        }
        CP_COMMIT();

        // ---- QK^T streamed per n-tile: s (transient) -> p -> Ps, lsum ----
#pragma unroll
        for (int nt = 0; nt < 8; nt++) {
            float s[4] = {0.f, 0.f, 0.f, 0.f};
#pragma unroll
            for (int kt = 0; kt < 8; kt++) {
                uint32_t b0 = __float_as_uint(sm[fk + (nt * 8 + gid) * SK + kt * 8 + qid]);
                uint32_t b1 = __float_as_uint(sm[fk + (nt * 8 + gid) * SK + kt * 8 + qid + 4]);
                mma_tf32(s, qa[kt][0], qa[kt][1], qa[kt][2], qa[kt][3], b0, b1);
            }
            // p = exp(s/8), tf32-rounded (consistent with PV mma inputs)
            float p0 = f2tf32f(__expf(s[0] * scale));
            float p1 = f2tf32f(__expf(s[1] * scale));
            float p2 = f2tf32f(__expf(s[2] * scale));
            float p3 = f2tf32f(__expf(s[3] * scale));
            lA += p0 + p1;
            lB += p2 + p3;
            *(float2*)&sm[FPS + (w16 + gid)     * SK + nt * 8 + 2 * qid] = make_float2(p0, p1);
            *(float2*)&sm[FPS + (w16 + gid + 8) * SK + nt * 8 + 2 * qid] = make_float2(p2, p3);
        }
        __syncwarp();   // Ps rows are warp-private: order STS before LDS

        // ---- O += P V ----
#pragma unroll
        for (int kt = 0; kt < 8; kt++) {
            uint32_t a0 = __float_as_uint(sm[FPS + (w16 + gid)     * SK + kt * 8 + qid]);
            uint32_t a1 = __float_as_uint(sm[FPS + (w16 + gid + 8) * SK + kt * 8 + qid]);
            uint32_t a2 = __float_as_uint(sm[FPS + (w16 + gid)     * SK + kt * 8 + qid + 4]);
            uint32_t a3 = __float_as_uint(sm[FPS + (w16 + gid + 8) * SK + kt * 8 + qid + 4]);
#pragma unroll
            for (int nt = 0; nt < 8; nt++) {
                uint32_t b0 = __float_as_uint(sm[fv + (kt * 8 + qid)     * SV + nt * 8 + gid]);
                uint32_t b1 = __float_as_uint(sm[fv + (kt * 8 + qid + 4) * SV + nt * 8 + gid]);
                mma_tf32(o[nt], a0, a1, a2, a3, b0, b1);
            }
        }

        CP_WAIT0();        // tile t+1 fill done
        __syncthreads();   // all warps done reading bufs before reuse
    }

    // Row sums: reduce across the 4 qid lanes of each quad.
    lA += __shfl_xor_sync(0xFFFFFFFFu, lA, 1);
    lA += __shfl_xor_sync(0xFFFFFFFFu, lA, 2);
    lB += __shfl_xor_sync(0xFFFFFFFFu, lB, 1);
    lB += __shfl_xor_sync(0xFFFFFFFFu, lB, 2);

    // Epilogue: O / (l + 1)   [restricted softmax, margin = 0]
    float invA = 1.0f / (lA + 1.0f);
    float invB = 1.0f / (lB + 1.0f);
    float* obase = out + ((size_t)b * SS + qt * 128) * CC + h * DD;
#pragma unroll
    for (int nt = 0; nt < 8; nt++) {
        int c = nt * 8 + 2 * qid;
        *(float2*)&obase[(size_t)(w16 + gid)     * CC + c] =
            make_float2(o[nt][0] * invA, o[nt][1] * invA);
        *(float2*)&obase[(size_t)(w16 + gid + 8) * CC + c] =
            make_float2(o[nt][2] * invB, o[nt][3] * invB);
    }
}

// ---------------------------------------------------------------------------
// Binding: dict/insertion order (verified R6-R13).
// ---------------------------------------------------------------------------
extern "C" void kernel_launch(void* const* d_in, const int* in_sizes, int n_in,
                              void* d_out, int out_size)
{
    const float* query = (const float*)d_in[0];
    const float* key   = (const float*)d_in[1];
    const float* value = (const float*)d_in[2];
    const float* wq    = (const float*)d_in[3];
    const float* wk    = (const float*)d_in[4];
    const float* wv    = (const float*)d_in[5];
    const float* bq    = (const float*)d_in[6];
    const float* bk    = (const float*)d_in[7];
    const float* bv    = (const float*)d_in[8];
    float* out = (float*)d_out;

    cudaFuncSetAttribute(attn_kernel, cudaFuncAttributeMaxDynamicSharedMemorySize,
                         ATTN_SMEM);

    dim3 pgrid(BB * SS / 128, CC / 128, 3);
    proj_kernel<<<pgrid, 256>>>(query, key, value, wq, wk, wv, bq, bk, bv);

    dim3 agrid(SS / 128, HH, BB);
    attn_kernel<<<agrid, 256, ATTN_SMEM>>>(out);
}

// round 15
// speedup vs baseline: 1.5595x; 1.5595x over previous
#include <cuda_runtime.h>
#include <cuda_fp16.h>
#include <math.h>
#include <stdint.h>

// Problem constants
#define BB 2
#define SS 2048
#define CC 1024
#define HH 16
#define DD 64
#define GG 4
#define ICG 256
#define OCG 256

// Projected tensors in half precision (fp16 mma path).
// g_qh/g_kh: [b][s][c];  g_vt: [b][h][d][s]  (V transposed for PV B-frags)
__device__ __half g_qh[BB * SS * CC];
__device__ __half g_kh[BB * SS * CC];
__device__ __half g_vt[BB * HH * DD * SS];

// ---------------------------------------------------------------------------
// helpers
// ---------------------------------------------------------------------------
__device__ __forceinline__ uint32_t f2tf32(float x) {
    uint32_t u;
    asm("cvt.rna.tf32.f32 %0, %1;" : "=r"(u) : "f"(x));
    return u;
}
__device__ __forceinline__ float f2tf32f(float x) {
    return __uint_as_float(f2tf32(x));
}
__device__ __forceinline__ uint32_t smem_u32(const void* p) {
    uint32_t a;
    asm("{ .reg .u64 t; cvta.to.shared.u64 t, %1; cvt.u32.u64 %0, t; }"
        : "=r"(a) : "l"(p));
    return a;
}
__device__ __forceinline__ uint32_t pack_h2(float x, float y) {
    __half2 h = __floats2half2_rn(x, y);   // low = x, high = y
    return *(uint32_t*)&h;
}
#define CP_ASYNC16(dst_u32, src_ptr) \
    asm volatile("cp.async.ca.shared.global [%0], [%1], 16;" \
                 :: "r"(dst_u32), "l"(src_ptr))
#define CP_COMMIT() asm volatile("cp.async.commit_group;")
#define CP_WAIT0()  asm volatile("cp.async.wait_group 0;")

__device__ __forceinline__ void mma_tf32(float d[4], uint32_t a0, uint32_t a1,
                                         uint32_t a2, uint32_t a3,
                                         uint32_t b0, uint32_t b1) {
    asm volatile(
        "mma.sync.aligned.m16n8k8.row.col.f32.tf32.tf32.f32 "
        "{%0,%1,%2,%3}, {%4,%5,%6,%7}, {%8,%9}, {%0,%1,%2,%3};"
        : "+f"(d[0]), "+f"(d[1]), "+f"(d[2]), "+f"(d[3])
        : "r"(a0), "r"(a1), "r"(a2), "r"(a3), "r"(b0), "r"(b1));
}

__device__ __forceinline__ void mma_f16(float d[4], uint32_t a0, uint32_t a1,
                                        uint32_t a2, uint32_t a3,
                                        uint32_t b0, uint32_t b1) {
    asm volatile(
        "mma.sync.aligned.m16n8k16.row.col.f32.f16.f16.f32 "
        "{%0,%1,%2,%3}, {%4,%5,%6,%7}, {%8,%9}, {%0,%1,%2,%3};"
        : "+f"(d[0]), "+f"(d[1]), "+f"(d[2]), "+f"(d[3])
        : "r"(a0), "r"(a1), "r"(a2), "r"(a3), "r"(b0), "r"(b1));
}

// ---------------------------------------------------------------------------
// Grouped linear projection on tensor cores (tf32 warp-mma, fp32 accum).
// Epilogue now writes HALF outputs: q,k -> [b][s][c]; v -> transposed [b][h][d][s].
// ---------------------------------------------------------------------------
#define PSTRA 36
#define PSTRB 136

__global__ __launch_bounds__(256) void proj_kernel(
    const float* __restrict__ qin, const float* __restrict__ kin,
    const float* __restrict__ vin,
    const float* __restrict__ wq, const float* __restrict__ wk,
    const float* __restrict__ wv,
    const float* __restrict__ bq, const float* __restrict__ bk,
    const float* __restrict__ bv)
{
    const float* src; const float* w; const float* bias;
    if (blockIdx.z == 0)      { src = qin; w = wq; bias = bq; }
    else if (blockIdx.z == 1) { src = kin; w = wk; bias = bk; }
    else                      { src = vin; w = wv; bias = bv; }

    const int row0 = blockIdx.x * 128;
    const int col0 = blockIdx.y * 128;
    const int g    = col0 / OCG;
    const int nb   = col0 % OCG;

    __shared__ float As[128 * PSTRA];
    __shared__ float Bs[32 * PSTRB];

    const int tid  = threadIdx.x;
    const int lane = tid & 31;
    const int warp = tid >> 5;
    const int gid  = lane >> 2;
    const int qid  = lane & 3;
    const int wm   = (warp >> 1) * 32;
    const int wn   = (warp & 1) * 64;

    float acc[2][8][4];
#pragma unroll
    for (int f = 0; f < 2; f++)
#pragma unroll
        for (int nt = 0; nt < 8; nt++)
#pragma unroll
            for (int j = 0; j < 4; j++) acc[f][nt][j] = 0.0f;

    const float* srcb = src + (size_t)row0 * CC + g * ICG;
    const float* wb   = w + (size_t)g * ICG * OCG + nb;

    for (int k0 = 0; k0 < ICG; k0 += 32) {
        for (int e = tid; e < 128 * 32; e += 256) {
            int r = e >> 5, kk = e & 31;
            As[r * PSTRA + kk] = f2tf32f(srcb[(size_t)r * CC + k0 + kk]);
        }
        for (int e = tid; e < 32 * 128; e += 256) {
            int kk = e >> 7, n = e & 127;
            Bs[kk * PSTRB + n] = f2tf32f(wb[(size_t)(k0 + kk) * OCG + n]);
        }
        __syncthreads();

#pragma unroll
        for (int kt = 0; kt < 4; kt++) {
            uint32_t a[2][4];
#pragma unroll
            for (int f = 0; f < 2; f++) {
                int rb = wm + f * 16;
                a[f][0] = __float_as_uint(As[(rb + gid)     * PSTRA + kt * 8 + qid]);
                a[f][1] = __float_as_uint(As[(rb + gid + 8) * PSTRA + kt * 8 + qid]);
                a[f][2] = __float_as_uint(As[(rb + gid)     * PSTRA + kt * 8 + qid + 4]);
                a[f][3] = __float_as_uint(As[(rb + gid + 8) * PSTRA + kt * 8 + qid + 4]);
            }
#pragma unroll
            for (int nt = 0; nt < 8; nt++) {
                uint32_t b0 = __float_as_uint(Bs[(kt * 8 + qid)     * PSTRB + wn + nt * 8 + gid]);
                uint32_t b1 = __float_as_uint(Bs[(kt * 8 + qid + 4) * PSTRB + wn + nt * 8 + gid]);
                mma_tf32(acc[0][nt], a[0][0], a[0][1], a[0][2], a[0][3], b0, b1);
                mma_tf32(acc[1][nt], a[1][0], a[1][1], a[1][2], a[1][3], b0, b1);
            }
        }
        __syncthreads();
    }

    // Epilogue: add bias, write half outputs.
    if (blockIdx.z != 2) {
        __half* outh = (blockIdx.z == 0) ? g_qh : g_kh;
#pragma unroll
        for (int f = 0; f < 2; f++) {
            int rb = row0 + wm + f * 16;
#pragma unroll
            for (int nt = 0; nt < 8; nt++) {
                int c = col0 + wn + nt * 8 + 2 * qid;
                float b0v = bias[c], b1v = bias[c + 1];
                *(uint32_t*)&outh[(size_t)(rb + gid) * CC + c] =
                    pack_h2(acc[f][nt][0] + b0v, acc[f][nt][1] + b1v);
                *(uint32_t*)&outh[(size_t)(rb + gid + 8) * CC + c] =
                    pack_h2(acc[f][nt][2] + b0v, acc[f][nt][3] + b1v);
            }
        }
    } else {
        // V: write transposed g_vt[((b*HH+h)*DD+d)*SS + s]
#pragma unroll
        for (int f = 0; f < 2; f++) {
            int rb = row0 + wm + f * 16;
#pragma unroll
            for (int nt = 0; nt < 8; nt++) {
                int c = col0 + wn + nt * 8 + 2 * qid;
                float b0v = bias[c], b1v = bias[c + 1];
                int hh = c >> 6, dd = c & 63;
#pragma unroll
                for (int rr = 0; rr < 2; rr++) {
                    int r = rb + gid + rr * 8;
                    int bb = r >> 11, ss = r & 2047;
                    size_t base = ((size_t)(bb * HH + hh) * DD + dd) * SS + ss;
                    g_vt[base]      = __float2half_rn(acc[f][nt][rr * 2 + 0] + b0v);
                    g_vt[base + SS] = __float2half_rn(acc[f][nt][rr * 2 + 1] + b1v);
                }
            }
        }
    }
}

// ---------------------------------------------------------------------------
// Flash attention v5: fp16 mma m16n8k16 (same 11-bit significand as tf32,
// half the LDS bytes and mma instructions per FLOP). M=16/warp, 256 threads,
// Q in registers (16 regs), no-max restricted softmax
// (out = exp(s)/(sum exp(s)+1); max cancels algebraically, |s| <~ 3),
// streaming S->P, double-buffered cp.async K/V fills.
// Smem (halves, stride 72): 2 x (K 64x72 + VT 64x72) + Ps 128x72 = 55,296 B.
// Grid: (16, 16, 2), 2 CTAs/SM.
// ---------------------------------------------------------------------------
#define KTILE 64
#define SKH 72
#define FK0H 0
#define FV0H (KTILE * SKH)                // 4608
#define FK1H (FV0H + KTILE * SKH)         // 9216
#define FV1H (FK1H + KTILE * SKH)         // 13824
#define FPSH (FV1H + KTILE * SKH)         // 18432
#define ATTN_SMEM ((FPSH + 128 * SKH) * 2)  // 55,296 B
#define NTILE (SS / KTILE)

__global__ __launch_bounds__(256, 2) void attn_kernel(float* __restrict__ out)
{
    extern __shared__ __half smh[];
    const uint32_t sb = smem_u32(smh);

    const int qt = blockIdx.x;
    const int h  = blockIdx.y;
    const int b  = blockIdx.z;

    const int tid  = threadIdx.x;
    const int lane = tid & 31;
    const int warp = tid >> 5;
    const int gid  = lane >> 2;
    const int qid  = lane & 3;
    const int w16  = warp * 16;

    const float scale = 0.125f;   // 1/sqrt(64)

    const __half* qb  = g_qh + ((size_t)b * SS + qt * 128) * CC + h * DD;
    const __half* kbb = g_kh + (size_t)b * SS * CC + h * DD;
    const __half* vtb = g_vt + (size_t)(b * HH + h) * DD * SS;   // [d][s]

    // Prologue: stage Q (128 x 64 halves) into buf1 region; K/V t=0 -> buf0.
#pragma unroll
    for (int e = tid; e < 128 * 8; e += 256) {
        int r = e >> 3, c8 = (e & 7) * 8;
        CP_ASYNC16(sb + (FK1H + r * SKH + c8) * 2, qb + (size_t)r * CC + c8);
    }
    CP_COMMIT();
#pragma unroll
    for (int e = tid; e < KTILE * 8; e += 256) {
        int r = e >> 3, c8 = (e & 7) * 8;
        CP_ASYNC16(sb + (FK0H + r * SKH + c8) * 2, kbb + (size_t)r * CC + c8);
        CP_ASYNC16(sb + (FV0H + r * SKH + c8) * 2, vtb + (size_t)r * SS + c8);
    }
    CP_COMMIT();
    CP_WAIT0();
    __syncthreads();

    // Q A-fragments -> registers (held for all tiles). 16 regs.
    uint32_t qa[4][4];
#pragma unroll
    for (int kt = 0; kt < 4; kt++) {
        qa[kt][0] = *(uint32_t*)&smh[FK1H + (w16 + gid)     * SKH + kt * 16 + 2 * qid];
        qa[kt][1] = *(uint32_t*)&smh[FK1H + (w16 + gid + 8) * SKH + kt * 16 + 2 * qid];
        qa[kt][2] = *(uint32_t*)&smh[FK1H + (w16 + gid)     * SKH + kt * 16 + 2 * qid + 8];
        qa[kt][3] = *(uint32_t*)&smh[FK1H + (w16 + gid + 8) * SKH + kt * 16 + 2 * qid + 8];
    }
    __syncthreads();   // buf1 free for t=1 prefetch

    float o[8][4];
    float lA = 0.0f, lB = 0.0f;
#pragma unroll
    for (int nt = 0; nt < 8; nt++)
#pragma unroll
        for (int j = 0; j < 4; j++) o[nt][j] = 0.0f;

    for (int t = 0; t < NTILE; t++) {
        const int cur = t & 1;
        const int fk  = cur ? FK1H : FK0H;
        const int fv  = cur ? FV1H : FV0H;

        // Prefetch tile t+1 into the other buffer (hidden behind compute).
        if (t + 1 < NTILE) {
            const int nfk = cur ? FK0H : FK1H;
            const int nfv = cur ? FV0H : FV1H;
            const __half* kn = kbb + (size_t)(t + 1) * KTILE * CC;
            const __half* vn = vtb + (t + 1) * KTILE;
#pragma unroll
            for (int e = tid; e < KTILE * 8; e += 256) {
                int r = e >> 3, c8 = (e & 7) * 8;
                CP_ASYNC16(sb + (nfk + r * SKH + c8) * 2, kn + (size_t)r * CC + c8);
                CP_ASYNC16(sb + (nfv + r * SKH + c8) * 2, vn + (size_t)r * SS + c8);
            }
        }
        CP_COMMIT();

        // ---- QK^T streamed per n-tile: s (transient) -> p -> Ps, lsum ----
#pragma unroll
        for (int nt = 0; nt < 8; nt++) {
            float s[4] = {0.f, 0.f, 0.f, 0.f};
#pragma unroll
            for (int kt = 0; kt < 4; kt++) {
                uint32_t b0 = *(uint32_t*)&smh[fk + (nt * 8 + gid) * SKH + kt * 16 + 2 * qid];
                uint32_t b1 = *(uint32_t*)&smh[fk + (nt * 8 + gid) * SKH + kt * 16 + 2 * qid + 8];
                mma_f16(s, qa[kt][0], qa[kt][1], qa[kt][2], qa[kt][3], b0, b1);
            }
            float p0 = __expf(s[0] * scale);
            float p1 = __expf(s[1] * scale);
            float p2 = __expf(s[2] * scale);
            float p3 = __expf(s[3] * scale);
            lA += p0 + p1;
            lB += p2 + p3;
            *(uint32_t*)&smh[FPSH + (w16 + gid)     * SKH + nt * 8 + 2 * qid] = pack_h2(p0, p1);
            *(uint32_t*)&smh[FPSH + (w16 + gid + 8) * SKH + nt * 8 + 2 * qid] = pack_h2(p2, p3);
        }
        __syncwarp();   // Ps rows are warp-private: order STS before LDS

        // ---- O += P V ----
#pragma unroll
        for (int kt = 0; kt < 4; kt++) {
            uint32_t a0 = *(uint32_t*)&smh[FPSH + (w16 + gid)     * SKH + kt * 16 + 2 * qid];
            uint32_t a1 = *(uint32_t*)&smh[FPSH + (w16 + gid + 8) * SKH + kt * 16 + 2 * qid];
            uint32_t a2 = *(uint32_t*)&smh[FPSH + (w16 + gid)     * SKH + kt * 16 + 2 * qid + 8];
            uint32_t a3 = *(uint32_t*)&smh[FPSH + (w16 + gid + 8) * SKH + kt * 16 + 2 * qid + 8];
#pragma unroll
            for (int nt = 0; nt < 8; nt++) {
                // B[k=key][n=d]; VT[d][key]: half2 along key is contiguous.
                uint32_t b0 = *(uint32_t*)&smh[fv + (nt * 8 + gid) * SKH + kt * 16 + 2 * qid];
                uint32_t b1 = *(uint32_t*)&smh[fv + (nt * 8 + gid) * SKH + kt * 16 + 2 * qid + 8];
                mma_f16(o[nt], a0, a1, a2, a3, b0, b1);
            }
        }

        CP_WAIT0();        // tile t+1 fill done
        __syncthreads();   // all warps done reading bufs before reuse
    }

    // Row sums: reduce across the 4 qid lanes of each quad.
    lA += __shfl_xor_sync(0xFFFFFFFFu, lA, 1);
    lA += __shfl_xor_sync(0xFFFFFFFFu, lA, 2);
    lB += __shfl_xor_sync(0xFFFFFFFFu, lB, 1);
    lB += __shfl_xor_sync(0xFFFFFFFFu, lB, 2);

    // Epilogue: O / (l + 1)   [restricted softmax, margin = 0]
    float invA = 1.0f / (lA + 1.0f);
    float invB = 1.0f / (lB + 1.0f);
    float* obase = out + ((size_t)b * SS + qt * 128) * CC + h * DD;
#pragma unroll
    for (int nt = 0; nt < 8; nt++) {
        int c = nt * 8 + 2 * qid;
        *(float2*)&obase[(size_t)(w16 + gid)     * CC + c] =
            make_float2(o[nt][0] * invA, o[nt][1] * invA);
        *(float2*)&obase[(size_t)(w16 + gid + 8) * CC + c] =
            make_float2(o[nt][2] * invB, o[nt][3] * invB);
    }
}

// ---------------------------------------------------------------------------
// Binding: dict/insertion order (verified R6-R14).
// ---------------------------------------------------------------------------
extern "C" void kernel_launch(void* const* d_in, const int* in_sizes, int n_in,
                              void* d_out, int out_size)
{
    const float* query = (const float*)d_in[0];
    const float* key   = (const float*)d_in[1];
    const float* value = (const float*)d_in[2];
    const float* wq    = (const float*)d_in[3];
    const float* wk    = (const float*)d_in[4];
    const float* wv    = (const float*)d_in[5];
    const float* bq    = (const float*)d_in[6];
    const float* bk    = (const float*)d_in[7];
    const float* bv    = (const float*)d_in[8];
    float* out = (float*)d_out;

    cudaFuncSetAttribute(attn_kernel, cudaFuncAttributeMaxDynamicSharedMemorySize,
                         ATTN_SMEM);

    dim3 pgrid(BB * SS / 128, CC / 128, 3);
    proj_kernel<<<pgrid, 256>>>(query, key, value, wq, wk, wv, bq, bk, bv);

    dim3 agrid(SS / 128, HH, BB);
    attn_kernel<<<agrid, 256, ATTN_SMEM>>>(out);
}

// round 16
// speedup vs baseline: 2.3472x; 1.5051x over previous
#include <cuda_runtime.h>
#include <cuda_fp16.h>
#include <math.h>
#include <stdint.h>

// Problem constants
#define BB 2
#define SS 2048
#define CC 1024
#define HH 16
#define DD 64
#define GG 4
#define ICG 256
#define OCG 256

// Half-precision staging buffers
__device__ __half g_xq[BB * SS * CC];        // inputs converted to half
__device__ __half g_xk[BB * SS * CC];
__device__ __half g_xv[BB * SS * CC];
__device__ __half g_wt[3 * GG * ICG * OCG];  // weights: [proj][g][n][k] (transposed)

// Projected tensors (half): q,k: [b][s][c]; vt: [b][h][d][s]
__device__ __half g_qh[BB * SS * CC];
__device__ __half g_kh[BB * SS * CC];
__device__ __half g_vt[BB * HH * DD * SS];

// ---------------------------------------------------------------------------
// helpers
// ---------------------------------------------------------------------------
__device__ __forceinline__ uint32_t smem_u32(const void* p) {
    uint32_t a;
    asm("{ .reg .u64 t; cvta.to.shared.u64 t, %1; cvt.u32.u64 %0, t; }"
        : "=r"(a) : "l"(p));
    return a;
}
__device__ __forceinline__ uint32_t pack_h2(float x, float y) {
    __half2 h = __floats2half2_rn(x, y);
    return *(uint32_t*)&h;
}
#define CP_ASYNC16(dst_u32, src_ptr) \
    asm volatile("cp.async.ca.shared.global [%0], [%1], 16;" \
                 :: "r"(dst_u32), "l"(src_ptr))
#define CP_COMMIT() asm volatile("cp.async.commit_group;")
#define CP_WAIT0()  asm volatile("cp.async.wait_group 0;")

__device__ __forceinline__ void mma_f16(float d[4], uint32_t a0, uint32_t a1,
                                        uint32_t a2, uint32_t a3,
                                        uint32_t b0, uint32_t b1) {
    asm volatile(
        "mma.sync.aligned.m16n8k16.row.col.f32.f16.f16.f32 "
        "{%0,%1,%2,%3}, {%4,%5,%6,%7}, {%8,%9}, {%0,%1,%2,%3};"
        : "+f"(d[0]), "+f"(d[1]), "+f"(d[2]), "+f"(d[3])
        : "r"(a0), "r"(a1), "r"(a2), "r"(a3), "r"(b0), "r"(b1));
}

// ---------------------------------------------------------------------------
// Prep kernels: convert activations to half; transpose+convert weights.
// ---------------------------------------------------------------------------
__global__ __launch_bounds__(256) void cvt_act(
    const float* __restrict__ q, const float* __restrict__ k,
    const float* __restrict__ v)
{
    size_t i = ((size_t)blockIdx.x * 256 + threadIdx.x) * 4;
    if (i >= (size_t)BB * SS * CC) return;
    const float* s = (blockIdx.y == 0) ? q : (blockIdx.y == 1) ? k : v;
    __half* d = (blockIdx.y == 0) ? g_xq : (blockIdx.y == 1) ? g_xk : g_xv;
    float4 x = *(const float4*)(s + i);
    *(uint32_t*)(d + i)     = pack_h2(x.x, x.y);
    *(uint32_t*)(d + i + 2) = pack_h2(x.z, x.w);
}

__global__ __launch_bounds__(256) void cvt_wt(
    const float* __restrict__ wq, const float* __restrict__ wk,
    const float* __restrict__ wv)
{
    int i = blockIdx.x * 256 + threadIdx.x;     // over GG*ICG*OCG = 262144
    const float* w = (blockIdx.y == 0) ? wq : (blockIdx.y == 1) ? wk : wv;
    __half* dst = g_wt + (size_t)blockIdx.y * GG * ICG * OCG;
    int g = i >> 16, k = (i >> 8) & 255, n = i & 255;   // i = ((g*ICG)+k)*OCG+n
    dst[((size_t)(g * OCG + n)) * ICG + k] = __float2half_rn(w[i]);
}

// ---------------------------------------------------------------------------
// Grouped linear projection, fp16 mma m16n8k16, cp.async double-buffered.
// Block 256 thr = 8 warps, tile 128(M)x128(N), warp tile 32x64
// (wm = (warp>>1)*32, wn = (warp&1)*64). K = 256 in 4 chunks of 64.
// A smem [m][k] stride 72 halves; B smem [n][k] stride 72 (wt pre-transposed).
// Smem: 2 x (A 128x72 + B 128x72) halves = 73,728 B -> 2 CTAs/SM.
// Grid: (32, 8, 3).
// ---------------------------------------------------------------------------
#define WSTR 72
#define PA0 0
#define PB0 (128 * WSTR)
#define PA1 (2 * 128 * WSTR)
#define PB1 (3 * 128 * WSTR)
#define PROJ_SMEM (4 * 128 * WSTR * 2)

__global__ __launch_bounds__(256, 2) void proj16_kernel(
    const float* __restrict__ bq, const float* __restrict__ bk,
    const float* __restrict__ bv)
{
    extern __shared__ __half ps[];
    const uint32_t sb = smem_u32(ps);

    const int z = blockIdx.z;
    const __half* src = (z == 0) ? g_xq : (z == 1) ? g_xk : g_xv;
    const float* bias = (z == 0) ? bq : (z == 1) ? bk : bv;
    const __half* wt  = g_wt + (size_t)z * GG * ICG * OCG;

    const int row0 = blockIdx.x * 128;
    const int col0 = blockIdx.y * 128;
    const int g    = col0 / OCG;
    const int nb   = col0 % OCG;

    const int tid  = threadIdx.x;
    const int lane = tid & 31;
    const int warp = tid >> 5;
    const int gid  = lane >> 2;
    const int qid  = lane & 3;
    const int wm   = (warp >> 1) * 32;
    const int wn   = (warp & 1) * 64;

    const __half* srcb = src + (size_t)row0 * CC + g * ICG;      // [m][k]
    const __half* wtb  = wt + (size_t)(g * OCG + nb) * ICG;      // [n][k]

    float acc[2][8][4];
#pragma unroll
    for (int f = 0; f < 2; f++)
#pragma unroll
        for (int nt = 0; nt < 8; nt++)
#pragma unroll
            for (int j = 0; j < 4; j++) acc[f][nt][j] = 0.0f;

    // Fill chunk 0 into buf0.
#pragma unroll
    for (int e = tid; e < 128 * 8; e += 256) {
        int r = e >> 3, c8 = (e & 7) * 8;
        CP_ASYNC16(sb + (PA0 + r * WSTR + c8) * 2, srcb + (size_t)r * CC + c8);
        CP_ASYNC16(sb + (PB0 + r * WSTR + c8) * 2, wtb + (size_t)r * ICG + c8);
    }
    CP_COMMIT();
    CP_WAIT0();
    __syncthreads();

    for (int c = 0; c < 4; c++) {
        const int cur = c & 1;
        const int fa = cur ? PA1 : PA0;
        const int fb = cur ? PB1 : PB0;

        if (c + 1 < 4) {
            const int na = cur ? PA0 : PA1;
            const int nbuf = cur ? PB0 : PB1;
            const int k0 = (c + 1) * 64;
#pragma unroll
            for (int e = tid; e < 128 * 8; e += 256) {
                int r = e >> 3, c8 = (e & 7) * 8;
                CP_ASYNC16(sb + (na + r * WSTR + c8) * 2,
                           srcb + (size_t)r * CC + k0 + c8);
                CP_ASYNC16(sb + (nbuf + r * WSTR + c8) * 2,
                           wtb + (size_t)r * ICG + k0 + c8);
            }
        }
        CP_COMMIT();

#pragma unroll
        for (int ks = 0; ks < 4; ks++) {
            uint32_t a[2][4];
#pragma unroll
            for (int f = 0; f < 2; f++) {
                int rb = wm + f * 16;
                a[f][0] = *(uint32_t*)&ps[fa + (rb + gid)     * WSTR + ks * 16 + 2 * qid];
                a[f][1] = *(uint32_t*)&ps[fa + (rb + gid + 8) * WSTR + ks * 16 + 2 * qid];
                a[f][2] = *(uint32_t*)&ps[fa + (rb + gid)     * WSTR + ks * 16 + 2 * qid + 8];
                a[f][3] = *(uint32_t*)&ps[fa + (rb + gid + 8) * WSTR + ks * 16 + 2 * qid + 8];
            }
#pragma unroll
            for (int nt = 0; nt < 8; nt++) {
                uint32_t b0 = *(uint32_t*)&ps[fb + (wn + nt * 8 + gid) * WSTR + ks * 16 + 2 * qid];
                uint32_t b1 = *(uint32_t*)&ps[fb + (wn + nt * 8 + gid) * WSTR + ks * 16 + 2 * qid + 8];
                mma_f16(acc[0][nt], a[0][0], a[0][1], a[0][2], a[0][3], b0, b1);
                mma_f16(acc[1][nt], a[1][0], a[1][1], a[1][2], a[1][3], b0, b1);
            }
        }

        CP_WAIT0();
        __syncthreads();
    }

    // Epilogue: add bias; q,k -> g_qh/g_kh [b][s][c]; v -> g_vt [b][h][d][s].
    if (z != 2) {
        __half* outh = (z == 0) ? g_qh : g_kh;
#pragma unroll
        for (int f = 0; f < 2; f++) {
            int rb = row0 + wm + f * 16;
#pragma unroll
            for (int nt = 0; nt < 8; nt++) {
                int cc = col0 + wn + nt * 8 + 2 * qid;
                float b0v = bias[cc], b1v = bias[cc + 1];
                *(uint32_t*)&outh[(size_t)(rb + gid) * CC + cc] =
                    pack_h2(acc[f][nt][0] + b0v, acc[f][nt][1] + b1v);
                *(uint32_t*)&outh[(size_t)(rb + gid + 8) * CC + cc] =
                    pack_h2(acc[f][nt][2] + b0v, acc[f][nt][3] + b1v);
            }
        }
    } else {
#pragma unroll
        for (int f = 0; f < 2; f++) {
            int rb = row0 + wm + f * 16;
#pragma unroll
            for (int nt = 0; nt < 8; nt++) {
                int cc = col0 + wn + nt * 8 + 2 * qid;
                float b0v = bias[cc], b1v = bias[cc + 1];
                int hh = cc >> 6, dd = cc & 63;
#pragma unroll
                for (int rr = 0; rr < 2; rr++) {
                    int r = rb + gid + rr * 8;
                    int bb = r >> 11, ss = r & 2047;
                    size_t base = ((size_t)(bb * HH + hh) * DD + dd) * SS + ss;
                    g_vt[base]      = __float2half_rn(acc[f][nt][rr * 2 + 0] + b0v);
                    g_vt[base + SS] = __float2half_rn(acc[f][nt][rr * 2 + 1] + b1v);
                }
            }
        }
    }
}

// ---------------------------------------------------------------------------
// Flash attention (unchanged from R15): fp16 mma m16n8k16, M=16/warp,
// 256 threads, Q in registers, no-max restricted softmax
// (out = exp(s)/(sum exp(s)+1)), streaming S->P, double-buffered cp.async.
// Smem: 55,296 B. Grid: (16, 16, 2), 2 CTAs/SM.
// ---------------------------------------------------------------------------
#define KTILE 64
#define SKH 72
#define FK0H 0
#define FV0H (KTILE * SKH)
#define FK1H (FV0H + KTILE * SKH)
#define FV1H (FK1H + KTILE * SKH)
#define FPSH (FV1H + KTILE * SKH)
#define ATTN_SMEM ((FPSH + 128 * SKH) * 2)
#define NTILE (SS / KTILE)

__global__ __launch_bounds__(256, 2) void attn_kernel(float* __restrict__ out)
{
    extern __shared__ __half smh[];
    const uint32_t sb = smem_u32(smh);

    const int qt = blockIdx.x;
    const int h  = blockIdx.y;
    const int b  = blockIdx.z;

    const int tid  = threadIdx.x;
    const int lane = tid & 31;
    const int warp = tid >> 5;
    const int gid  = lane >> 2;
    const int qid  = lane & 3;
    const int w16  = warp * 16;

    const float scale = 0.125f;

    const __half* qb  = g_qh + ((size_t)b * SS + qt * 128) * CC + h * DD;
    const __half* kbb = g_kh + (size_t)b * SS * CC + h * DD;
    const __half* vtb = g_vt + (size_t)(b * HH + h) * DD * SS;

#pragma unroll
    for (int e = tid; e < 128 * 8; e += 256) {
        int r = e >> 3, c8 = (e & 7) * 8;
        CP_ASYNC16(sb + (FK1H + r * SKH + c8) * 2, qb + (size_t)r * CC + c8);
    }
    CP_COMMIT();
#pragma unroll
    for (int e = tid; e < KTILE * 8; e += 256) {
        int r = e >> 3, c8 = (e & 7) * 8;
        CP_ASYNC16(sb + (FK0H + r * SKH + c8) * 2, kbb + (size_t)r * CC + c8);
        CP_ASYNC16(sb + (FV0H + r * SKH + c8) * 2, vtb + (size_t)r * SS + c8);
    }
    CP_COMMIT();
    CP_WAIT0();
    __syncthreads();

    uint32_t qa[4][4];
#pragma unroll
    for (int kt = 0; kt < 4; kt++) {
        qa[kt][0] = *(uint32_t*)&smh[FK1H + (w16 + gid)     * SKH + kt * 16 + 2 * qid];
        qa[kt][1] = *(uint32_t*)&smh[FK1H + (w16 + gid + 8) * SKH + kt * 16 + 2 * qid];
        qa[kt][2] = *(uint32_t*)&smh[FK1H + (w16 + gid)     * SKH + kt * 16 + 2 * qid + 8];
        qa[kt][3] = *(uint32_t*)&smh[FK1H + (w16 + gid + 8) * SKH + kt * 16 + 2 * qid + 8];
    }
    __syncthreads();

    float o[8][4];
    float lA = 0.0f, lB = 0.0f;
#pragma unroll
    for (int nt = 0; nt < 8; nt++)
#pragma unroll
        for (int j = 0; j < 4; j++) o[nt][j] = 0.0f;

    for (int t = 0; t < NTILE; t++) {
        const int cur = t & 1;
        const int fk  = cur ? FK1H : FK0H;
        const int fv  = cur ? FV1H : FV0H;

        if (t + 1 < NTILE) {
            const int nfk = cur ? FK0H : FK1H;
            const int nfv = cur ? FV0H : FV1H;
            const __half* kn = kbb + (size_t)(t + 1) * KTILE * CC;
            const __half* vn = vtb + (t + 1) * KTILE;
#pragma unroll
            for (int e = tid; e < KTILE * 8; e += 256) {
                int r = e >> 3, c8 = (e & 7) * 8;
                CP_ASYNC16(sb + (nfk + r * SKH + c8) * 2, kn + (size_t)r * CC + c8);
                CP_ASYNC16(sb + (nfv + r * SKH + c8) * 2, vn + (size_t)r * SS + c8);
            }
        }
        CP_COMMIT();

#pragma unroll
        for (int nt = 0; nt < 8; nt++) {
            float s[4] = {0.f, 0.f, 0.f, 0.f};
#pragma unroll
            for (int kt = 0; kt < 4; kt++) {
                uint32_t b0 = *(uint32_t*)&smh[fk + (nt * 8 + gid) * SKH + kt * 16 + 2 * qid];
                uint32_t b1 = *(uint32_t*)&smh[fk + (nt * 8 + gid) * SKH + kt * 16 + 2 * qid + 8];
                mma_f16(s, qa[kt][0], qa[kt][1], qa[kt][2], qa[kt][3], b0, b1);
            }
            float p0 = __expf(s[0] * scale);
            float p1 = __expf(s[1] * scale);
            float p2 = __expf(s[2] * scale);
            float p3 = __expf(s[3] * scale);
            lA += p0 + p1;
            lB += p2 + p3;
            *(uint32_t*)&smh[FPSH + (w16 + gid)     * SKH + nt * 8 + 2 * qid] = pack_h2(p0, p1);
            *(uint32_t*)&smh[FPSH + (w16 + gid + 8) * SKH + nt * 8 + 2 * qid] = pack_h2(p2, p3);
        }
        __syncwarp();

#pragma unroll
        for (int kt = 0; kt < 4; kt++) {
            uint32_t a0 = *(uint32_t*)&smh[FPSH + (w16 + gid)     * SKH + kt * 16 + 2 * qid];
            uint32_t a1 = *(uint32_t*)&smh[FPSH + (w16 + gid + 8) * SKH + kt * 16 + 2 * qid];
            uint32_t a2 = *(uint32_t*)&smh[FPSH + (w16 + gid)     * SKH + kt * 16 + 2 * qid + 8];
            uint32_t a3 = *(uint32_t*)&smh[FPSH + (w16 + gid + 8) * SKH + kt * 16 + 2 * qid + 8];
#pragma unroll
            for (int nt = 0; nt < 8; nt++) {
                uint32_t b0 = *(uint32_t*)&smh[fv + (nt * 8 + gid) * SKH + kt * 16 + 2 * qid];
                uint32_t b1 = *(uint32_t*)&smh[fv + (nt * 8 + gid) * SKH + kt * 16 + 2 * qid + 8];
                mma_f16(o[nt], a0, a1, a2, a3, b0, b1);
            }
        }

        CP_WAIT0();
        __syncthreads();
    }

    lA += __shfl_xor_sync(0xFFFFFFFFu, lA, 1);
    lA += __shfl_xor_sync(0xFFFFFFFFu, lA, 2);
    lB += __shfl_xor_sync(0xFFFFFFFFu, lB, 1);
    lB += __shfl_xor_sync(0xFFFFFFFFu, lB, 2);

    float invA = 1.0f / (lA + 1.0f);
    float invB = 1.0f / (lB + 1.0f);
    float* obase = out + ((size_t)b * SS + qt * 128) * CC + h * DD;
#pragma unroll
    for (int nt = 0; nt < 8; nt++) {
        int c = nt * 8 + 2 * qid;
        *(float2*)&obase[(size_t)(w16 + gid)     * CC + c] =
            make_float2(o[nt][0] * invA, o[nt][1] * invA);
        *(float2*)&obase[(size_t)(w16 + gid + 8) * CC + c] =
            make_float2(o[nt][2] * invB, o[nt][3] * invB);
    }
}

// ---------------------------------------------------------------------------
// Binding: dict/insertion order (verified R6-R15).
// ---------------------------------------------------------------------------
extern "C" void kernel_launch(void* const* d_in, const int* in_sizes, int n_in,
                              void* d_out, int out_size)
{
    const float* query = (const float*)d_in[0];
    const float* key   = (const float*)d_in[1];
    const float* value = (const float*)d_in[2];
    const float* wq    = (const float*)d_in[3];
    const float* wk    = (const float*)d_in[4];
    const float* wv    = (const float*)d_in[5];
    const float* bq    = (const float*)d_in[6];
    const float* bk    = (const float*)d_in[7];
    const float* bv    = (const float*)d_in[8];
    float* out = (float*)d_out;

    cudaFuncSetAttribute(proj16_kernel, cudaFuncAttributeMaxDynamicSharedMemorySize,
                         PROJ_SMEM);
    cudaFuncSetAttribute(attn_kernel, cudaFuncAttributeMaxDynamicSharedMemorySize,
                         ATTN_SMEM);

    dim3 cgrid(BB * SS * CC / 4 / 256, 3);
    cvt_act<<<cgrid, 256>>>(query, key, value);
    dim3 wgrid(GG * ICG * OCG / 256, 3);
    cvt_wt<<<wgrid, 256>>>(wq, wk, wv);

    dim3 pgrid(BB * SS / 128, CC / 128, 3);
    proj16_kernel<<<pgrid, 256, PROJ_SMEM>>>(bq, bk, bv);

    dim3 agrid(SS / 128, HH, BB);
    attn_kernel<<<agrid, 256, ATTN_SMEM>>>(out);
}

// round 17
// speedup vs baseline: 2.6565x; 1.1318x over previous
#include <cuda_runtime.h>
#include <cuda_fp16.h>
#include <math.h>
#include <stdint.h>

// Problem constants
#define BB 2
#define SS 2048
#define CC 1024
#define HH 16
#define DD 64
#define GG 4
#define ICG 256
#define OCG 256

// Half-precision staging buffers
__device__ __half g_xq[BB * SS * CC];
__device__ __half g_xk[BB * SS * CC];
__device__ __half g_xv[BB * SS * CC];
__device__ __half g_wt[3 * GG * ICG * OCG];  // [proj][g][n][k]

// Projected tensors (half): q,k: [b][s][c]; vt: [b][h][d][s]
__device__ __half g_qh[BB * SS * CC];
__device__ __half g_kh[BB * SS * CC];
__device__ __half g_vt[BB * HH * DD * SS];

// ---------------------------------------------------------------------------
// helpers
// ---------------------------------------------------------------------------
__device__ __forceinline__ uint32_t smem_u32(const void* p) {
    uint32_t a;
    asm("{ .reg .u64 t; cvta.to.shared.u64 t, %1; cvt.u32.u64 %0, t; }"
        : "=r"(a) : "l"(p));
    return a;
}
__device__ __forceinline__ uint32_t pack_h2(float x, float y) {
    __half2 h = __floats2half2_rn(x, y);
    return *(uint32_t*)&h;
}
#define CP_ASYNC16(dst_u32, src_ptr) \
    asm volatile("cp.async.ca.shared.global [%0], [%1], 16;" \
                 :: "r"(dst_u32), "l"(src_ptr))
#define CP_COMMIT() asm volatile("cp.async.commit_group;")
#define CP_WAIT0()  asm volatile("cp.async.wait_group 0;")

__device__ __forceinline__ void mma_f16(float d[4], uint32_t a0, uint32_t a1,
                                        uint32_t a2, uint32_t a3,
                                        uint32_t b0, uint32_t b1) {
    asm volatile(
        "mma.sync.aligned.m16n8k16.row.col.f32.f16.f16.f32 "
        "{%0,%1,%2,%3}, {%4,%5,%6,%7}, {%8,%9}, {%0,%1,%2,%3};"
        : "+f"(d[0]), "+f"(d[1]), "+f"(d[2]), "+f"(d[3])
        : "r"(a0), "r"(a1), "r"(a2), "r"(a3), "r"(b0), "r"(b1));
}

// ---------------------------------------------------------------------------
// Prep kernels: convert activations to half; transpose+convert weights.
// ---------------------------------------------------------------------------
__global__ __launch_bounds__(256) void cvt_act(
    const float* __restrict__ q, const float* __restrict__ k,
    const float* __restrict__ v)
{
    size_t i = ((size_t)blockIdx.x * 256 + threadIdx.x) * 4;
    if (i >= (size_t)BB * SS * CC) return;
    const float* s = (blockIdx.y == 0) ? q : (blockIdx.y == 1) ? k : v;
    __half* d = (blockIdx.y == 0) ? g_xq : (blockIdx.y == 1) ? g_xk : g_xv;
    float4 x = *(const float4*)(s + i);
    *(uint32_t*)(d + i)     = pack_h2(x.x, x.y);
    *(uint32_t*)(d + i + 2) = pack_h2(x.z, x.w);
}

__global__ __launch_bounds__(256) void cvt_wt(
    const float* __restrict__ wq, const float* __restrict__ wk,
    const float* __restrict__ wv)
{
    int i = blockIdx.x * 256 + threadIdx.x;
    const float* w = (blockIdx.y == 0) ? wq : (blockIdx.y == 1) ? wk : wv;
    __half* dst = g_wt + (size_t)blockIdx.y * GG * ICG * OCG;
    int g = i >> 16, k = (i >> 8) & 255, n = i & 255;
    dst[((size_t)(g * OCG + n)) * ICG + k] = __float2half_rn(w[i]);
}

// ---------------------------------------------------------------------------
// Grouped linear projection, fp16 mma, cp.async double-buffered (R16, keep).
// ---------------------------------------------------------------------------
#define WSTR 72
#define PA0 0
#define PB0 (128 * WSTR)
#define PA1 (2 * 128 * WSTR)
#define PB1 (3 * 128 * WSTR)
#define PROJ_SMEM (4 * 128 * WSTR * 2)

__global__ __launch_bounds__(256, 2) void proj16_kernel(
    const float* __restrict__ bq, const float* __restrict__ bk,
    const float* __restrict__ bv)
{
    extern __shared__ __half ps[];
    const uint32_t sb = smem_u32(ps);

    const int z = blockIdx.z;
    const __half* src = (z == 0) ? g_xq : (z == 1) ? g_xk : g_xv;
    const float* bias = (z == 0) ? bq : (z == 1) ? bk : bv;
    const __half* wt  = g_wt + (size_t)z * GG * ICG * OCG;

    const int row0 = blockIdx.x * 128;
    const int col0 = blockIdx.y * 128;
    const int g    = col0 / OCG;
    const int nb   = col0 % OCG;

    const int tid  = threadIdx.x;
    const int lane = tid & 31;
    const int warp = tid >> 5;
    const int gid  = lane >> 2;
    const int qid  = lane & 3;
    const int wm   = (warp >> 1) * 32;
    const int wn   = (warp & 1) * 64;

    const __half* srcb = src + (size_t)row0 * CC + g * ICG;
    const __half* wtb  = wt + (size_t)(g * OCG + nb) * ICG;

    float acc[2][8][4];
#pragma unroll
    for (int f = 0; f < 2; f++)
#pragma unroll
        for (int nt = 0; nt < 8; nt++)
#pragma unroll
            for (int j = 0; j < 4; j++) acc[f][nt][j] = 0.0f;

#pragma unroll
    for (int e = tid; e < 128 * 8; e += 256) {
        int r = e >> 3, c8 = (e & 7) * 8;
        CP_ASYNC16(sb + (PA0 + r * WSTR + c8) * 2, srcb + (size_t)r * CC + c8);
        CP_ASYNC16(sb + (PB0 + r * WSTR + c8) * 2, wtb + (size_t)r * ICG + c8);
    }
    CP_COMMIT();
    CP_WAIT0();
    __syncthreads();

    for (int c = 0; c < 4; c++) {
        const int cur = c & 1;
        const int fa = cur ? PA1 : PA0;
        const int fb = cur ? PB1 : PB0;

        if (c + 1 < 4) {
            const int na = cur ? PA0 : PA1;
            const int nbuf = cur ? PB0 : PB1;
            const int k0 = (c + 1) * 64;
#pragma unroll
            for (int e = tid; e < 128 * 8; e += 256) {
                int r = e >> 3, c8 = (e & 7) * 8;
                CP_ASYNC16(sb + (na + r * WSTR + c8) * 2,
                           srcb + (size_t)r * CC + k0 + c8);
                CP_ASYNC16(sb + (nbuf + r * WSTR + c8) * 2,
                           wtb + (size_t)r * ICG + k0 + c8);
            }
        }
        CP_COMMIT();

#pragma unroll
        for (int ks = 0; ks < 4; ks++) {
            uint32_t a[2][4];
#pragma unroll
            for (int f = 0; f < 2; f++) {
                int rb = wm + f * 16;
                a[f][0] = *(uint32_t*)&ps[fa + (rb + gid)     * WSTR + ks * 16 + 2 * qid];
                a[f][1] = *(uint32_t*)&ps[fa + (rb + gid + 8) * WSTR + ks * 16 + 2 * qid];
                a[f][2] = *(uint32_t*)&ps[fa + (rb + gid)     * WSTR + ks * 16 + 2 * qid + 8];
                a[f][3] = *(uint32_t*)&ps[fa + (rb + gid + 8) * WSTR + ks * 16 + 2 * qid + 8];
            }
#pragma unroll
            for (int nt = 0; nt < 8; nt++) {
                uint32_t b0 = *(uint32_t*)&ps[fb + (wn + nt * 8 + gid) * WSTR + ks * 16 + 2 * qid];
                uint32_t b1 = *(uint32_t*)&ps[fb + (wn + nt * 8 + gid) * WSTR + ks * 16 + 2 * qid + 8];
                mma_f16(acc[0][nt], a[0][0], a[0][1], a[0][2], a[0][3], b0, b1);
                mma_f16(acc[1][nt], a[1][0], a[1][1], a[1][2], a[1][3], b0, b1);
            }
        }

        CP_WAIT0();
        __syncthreads();
    }

    if (z != 2) {
        __half* outh = (z == 0) ? g_qh : g_kh;
#pragma unroll
        for (int f = 0; f < 2; f++) {
            int rb = row0 + wm + f * 16;
#pragma unroll
            for (int nt = 0; nt < 8; nt++) {
                int cc = col0 + wn + nt * 8 + 2 * qid;
                float b0v = bias[cc], b1v = bias[cc + 1];
                *(uint32_t*)&outh[(size_t)(rb + gid) * CC + cc] =
                    pack_h2(acc[f][nt][0] + b0v, acc[f][nt][1] + b1v);
                *(uint32_t*)&outh[(size_t)(rb + gid + 8) * CC + cc] =
                    pack_h2(acc[f][nt][2] + b0v, acc[f][nt][3] + b1v);
            }
        }
    } else {
#pragma unroll
        for (int f = 0; f < 2; f++) {
            int rb = row0 + wm + f * 16;
#pragma unroll
            for (int nt = 0; nt < 8; nt++) {
                int cc = col0 + wn + nt * 8 + 2 * qid;
                float b0v = bias[cc], b1v = bias[cc + 1];
                int hh = cc >> 6, dd = cc & 63;
#pragma unroll
                for (int rr = 0; rr < 2; rr++) {
                    int r = rb + gid + rr * 8;
                    int bb = r >> 11, ss = r & 2047;
                    size_t base = ((size_t)(bb * HH + hh) * DD + dd) * SS + ss;
                    g_vt[base]      = __float2half_rn(acc[f][nt][rr * 2 + 0] + b0v);
                    g_vt[base + SS] = __float2half_rn(acc[f][nt][rr * 2 + 1] + b1v);
                }
            }
        }
    }
}

// ---------------------------------------------------------------------------
// Flash attention v6: P never touches smem. The QK^T C-fragment layout IS
// the PV A-fragment layout (lane (gid,qid): C cols nt*8+2qid(+1) at rows
// gid/gid+8 == A k-indices kt*16+2qid(+1)(+8) for nt=2kt/2kt+1), so
// p = exp(s) packs directly into A-frag registers. Removes 32 smem ops +
// syncwarp per warp-tile and the 18KB Ps buffer.
// M=16/warp, 256 threads, Q in registers, no-max restricted softmax
// (out = exp(s)/(sum exp(s)+1)), double-buffered cp.async K/V.
// Smem: 2 x (K 64x72 + VT 64x72) halves = 36,864 B. Grid: (16,16,2), 2 CTAs/SM.
// ---------------------------------------------------------------------------
#define KTILE 64
#define SKH 72
#define FK0H 0
#define FV0H (KTILE * SKH)
#define FK1H (FV0H + KTILE * SKH)
#define FV1H (FK1H + KTILE * SKH)
#define ATTN_SMEM ((FV1H + KTILE * SKH) * 2)   // 36,864 B
#define NTILE (SS / KTILE)

__global__ __launch_bounds__(256, 2) void attn_kernel(float* __restrict__ out)
{
    extern __shared__ __half smh[];
    const uint32_t sb = smem_u32(smh);

    const int qt = blockIdx.x;
    const int h  = blockIdx.y;
    const int b  = blockIdx.z;

    const int tid  = threadIdx.x;
    const int lane = tid & 31;
    const int warp = tid >> 5;
    const int gid  = lane >> 2;
    const int qid  = lane & 3;
    const int w16  = warp * 16;

    const float scale = 0.125f;

    const __half* qb  = g_qh + ((size_t)b * SS + qt * 128) * CC + h * DD;
    const __half* kbb = g_kh + (size_t)b * SS * CC + h * DD;
    const __half* vtb = g_vt + (size_t)(b * HH + h) * DD * SS;

    // Stage Q (128x72 halves = 9216) into buf1 (K1+V1 = 9216 halves exactly).
#pragma unroll
    for (int e = tid; e < 128 * 8; e += 256) {
        int r = e >> 3, c8 = (e & 7) * 8;
        CP_ASYNC16(sb + (FK1H + r * SKH + c8) * 2, qb + (size_t)r * CC + c8);
    }
    CP_COMMIT();
#pragma unroll
    for (int e = tid; e < KTILE * 8; e += 256) {
        int r = e >> 3, c8 = (e & 7) * 8;
        CP_ASYNC16(sb + (FK0H + r * SKH + c8) * 2, kbb + (size_t)r * CC + c8);
        CP_ASYNC16(sb + (FV0H + r * SKH + c8) * 2, vtb + (size_t)r * SS + c8);
    }
    CP_COMMIT();
    CP_WAIT0();
    __syncthreads();

    uint32_t qa[4][4];
#pragma unroll
    for (int kt = 0; kt < 4; kt++) {
        qa[kt][0] = *(uint32_t*)&smh[FK1H + (w16 + gid)     * SKH + kt * 16 + 2 * qid];
        qa[kt][1] = *(uint32_t*)&smh[FK1H + (w16 + gid + 8) * SKH + kt * 16 + 2 * qid];
        qa[kt][2] = *(uint32_t*)&smh[FK1H + (w16 + gid)     * SKH + kt * 16 + 2 * qid + 8];
        qa[kt][3] = *(uint32_t*)&smh[FK1H + (w16 + gid + 8) * SKH + kt * 16 + 2 * qid + 8];
    }
    __syncthreads();   // buf1 free for t=1 prefetch

    float o[8][4];
    float lA = 0.0f, lB = 0.0f;
#pragma unroll
    for (int nt = 0; nt < 8; nt++)
#pragma unroll
        for (int j = 0; j < 4; j++) o[nt][j] = 0.0f;

    for (int t = 0; t < NTILE; t++) {
        const int cur = t & 1;
        const int fk  = cur ? FK1H : FK0H;
        const int fv  = cur ? FV1H : FV0H;

        if (t + 1 < NTILE) {
            const int nfk = cur ? FK0H : FK1H;
            const int nfv = cur ? FV0H : FV1H;
            const __half* kn = kbb + (size_t)(t + 1) * KTILE * CC;
            const __half* vn = vtb + (t + 1) * KTILE;
#pragma unroll
            for (int e = tid; e < KTILE * 8; e += 256) {
                int r = e >> 3, c8 = (e & 7) * 8;
                CP_ASYNC16(sb + (nfk + r * SKH + c8) * 2, kn + (size_t)r * CC + c8);
                CP_ASYNC16(sb + (nfv + r * SKH + c8) * 2, vn + (size_t)r * SS + c8);
            }
        }
        CP_COMMIT();

        // ---- QK^T streamed: s (transient) -> p packed straight into
        //      PV A-fragments pa[kt][0..3] (layout identity, no smem) ----
        uint32_t pa[4][4];
#pragma unroll
        for (int nt = 0; nt < 8; nt++) {
            float s[4] = {0.f, 0.f, 0.f, 0.f};
#pragma unroll
            for (int kt = 0; kt < 4; kt++) {
                uint32_t b0 = *(uint32_t*)&smh[fk + (nt * 8 + gid) * SKH + kt * 16 + 2 * qid];
                uint32_t b1 = *(uint32_t*)&smh[fk + (nt * 8 + gid) * SKH + kt * 16 + 2 * qid + 8];
                mma_f16(s, qa[kt][0], qa[kt][1], qa[kt][2], qa[kt][3], b0, b1);
            }
            float p0 = __expf(s[0] * scale);
            float p1 = __expf(s[1] * scale);
            float p2 = __expf(s[2] * scale);
            float p3 = __expf(s[3] * scale);
            lA += p0 + p1;
            lB += p2 + p3;
            int akt = nt >> 1;
            if ((nt & 1) == 0) {
                pa[akt][0] = pack_h2(p0, p1);   // (row gid,   k lo)
                pa[akt][1] = pack_h2(p2, p3);   // (row gid+8, k lo)
            } else {
                pa[akt][2] = pack_h2(p0, p1);   // (row gid,   k hi)
                pa[akt][3] = pack_h2(p2, p3);   // (row gid+8, k hi)
            }
        }

        // ---- O += P V (A-frags already in registers) ----
#pragma unroll
        for (int kt = 0; kt < 4; kt++) {
#pragma unroll
            for (int nt = 0; nt < 8; nt++) {
                uint32_t b0 = *(uint32_t*)&smh[fv + (nt * 8 + gid) * SKH + kt * 16 + 2 * qid];
                uint32_t b1 = *(uint32_t*)&smh[fv + (nt * 8 + gid) * SKH + kt * 16 + 2 * qid + 8];
                mma_f16(o[nt], pa[kt][0], pa[kt][1], pa[kt][2], pa[kt][3], b0, b1);
            }
        }

        CP_WAIT0();
        __syncthreads();
    }

    lA += __shfl_xor_sync(0xFFFFFFFFu, lA, 1);
    lA += __shfl_xor_sync(0xFFFFFFFFu, lA, 2);
    lB += __shfl_xor_sync(0xFFFFFFFFu, lB, 1);
    lB += __shfl_xor_sync(0xFFFFFFFFu, lB, 2);

    float invA = 1.0f / (lA + 1.0f);
    float invB = 1.0f / (lB + 1.0f);
    float* obase = out + ((size_t)b * SS + qt * 128) * CC + h * DD;
#pragma unroll
    for (int nt = 0; nt < 8; nt++) {
        int c = nt * 8 + 2 * qid;
        *(float2*)&obase[(size_t)(w16 + gid)     * CC + c] =
            make_float2(o[nt][0] * invA, o[nt][1] * invA);
        *(float2*)&obase[(size_t)(w16 + gid + 8) * CC + c] =
            make_float2(o[nt][2] * invB, o[nt][3] * invB);
    }
}

// ---------------------------------------------------------------------------
// Binding: dict/insertion order (verified R6-R16).
// ---------------------------------------------------------------------------
extern "C" void kernel_launch(void* const* d_in, const int* in_sizes, int n_in,
                              void* d_out, int out_size)
{
    const float* query = (const float*)d_in[0];
    const float* key   = (const float*)d_in[1];
    const float* value = (const float*)d_in[2];
    const float* wq    = (const float*)d_in[3];
    const float* wk    = (const float*)d_in[4];
    const float* wv    = (const float*)d_in[5];
    const float* bq    = (const float*)d_in[6];
    const float* bk    = (const float*)d_in[7];
    const float* bv    = (const float*)d_in[8];
    float* out = (float*)d_out;

    cudaFuncSetAttribute(proj16_kernel, cudaFuncAttributeMaxDynamicSharedMemorySize,
                         PROJ_SMEM);
    cudaFuncSetAttribute(attn_kernel, cudaFuncAttributeMaxDynamicSharedMemorySize,
                         ATTN_SMEM);

    dim3 cgrid(BB * SS * CC / 4 / 256, 3);
    cvt_act<<<cgrid, 256>>>(query, key, value);
    dim3 wgrid(GG * ICG * OCG / 256, 3);
    cvt_wt<<<wgrid, 256>>>(wq, wk, wv);

    dim3 pgrid(BB * SS / 128, CC / 128, 3);
    proj16_kernel<<<pgrid, 256, PROJ_SMEM>>>(bq, bk, bv);

    dim3 agrid(SS / 128, HH, BB);
    attn_kernel<<<agrid, 256, ATTN_SMEM>>>(out);
}